// round 2
// baseline (speedup 1.0000x reference)
#include <cuda_runtime.h>

typedef unsigned long long ull;

#define CDIM 128
#define HW   65536
#define PT   128      // P tile per block
#define KC   32       // K chunk
#define XROW 320      // padded dup-X row: 16 chunks * (16 data + 4 pad) floats
#define SMEM_BYTES ((CDIM*CDIM + KC*XROW) * 4)   // 64KB Wt + 40KB dup-X = 104KB

__device__ float g_T1[CDIM*CDIM];
__device__ float g_T2[CDIM*CDIM];
__device__ float g_Wt[CDIM*CDIM];   // Wt[c][o] = W[o][c]
__device__ float g_bias[CDIM];

// ---------------------------------------------------------------------------
// Setup 1: T1 = amp_w @ G_re,  T2 = phase_w @ G_im      (each 128x128)
// T1[o][k] = (-1)^k * sum_c amp_w[o][c]*m[c]*cos(2*pi*c*k/128)
// T2[o][k] = -(-1)^k * sum_c phase_w[o][c]*m[c]*sin(2*pi*c*k/128)
// block = o, thread = k
// ---------------------------------------------------------------------------
__global__ void setup1_kernel(const float* __restrict__ amp_w,
                              const float* __restrict__ phase_w,
                              const float* __restrict__ freq_mask) {
    int o = blockIdx.x, k = threadIdx.x;
    __shared__ float AM[CDIM], PM[CDIM], CT[CDIM], ST[CDIM];
    float m = freq_mask[k];
    AM[k] = amp_w[o*CDIM + k] * m;
    PM[k] = phase_w[o*CDIM + k] * m;
    float s, c;
    sincospif(2.0f * (float)k / (float)CDIM, &s, &c);  // angle 2*pi*k/128
    CT[k] = c; ST[k] = s;
    __syncthreads();
    float t1 = 0.f, t2 = 0.f;
    #pragma unroll 8
    for (int cc = 0; cc < CDIM; cc++) {
        int idx = (cc * k) & (CDIM - 1);
        t1 += AM[cc] * CT[idx];
        t2 -= PM[cc] * ST[idx];
    }
    float sgnk = (k & 1) ? -1.f : 1.f;
    g_T1[o*CDIM + k] = t1 * sgnk;
    g_T2[o*CDIM + k] = t2 * sgnk;
}

// ---------------------------------------------------------------------------
// Setup 2: W[n][k] = ((-1)^n/128) * sum_j [cos(2*pi*n*j/128)*T1[j][k]
//                                          - sin(2*pi*n*j/128)*T2[j][k]]
// bias[n] likewise from amp_b/phase_b. Stores W transposed (Wt[c][o]).
// block = n, thread = k
// ---------------------------------------------------------------------------
__global__ void setup2_kernel(const float* __restrict__ amp_b,
                              const float* __restrict__ phase_b) {
    int n = blockIdx.x, k = threadIdx.x;
    __shared__ float CT[CDIM], ST[CDIM];
    float s, c;
    sincospif(2.0f * (float)k / (float)CDIM, &s, &c);
    CT[k] = c; ST[k] = s;
    __syncthreads();
    float acc = 0.f;
    #pragma unroll 8
    for (int j = 0; j < CDIM; j++) {
        int idx = (n * j) & (CDIM - 1);
        acc += CT[idx] * g_T1[j*CDIM + k] - ST[idx] * g_T2[j*CDIM + k];
    }
    float sc = ((n & 1) ? -1.f : 1.f) / (float)CDIM;
    g_Wt[k*CDIM + n] = acc * sc;          // transposed store: Wt[c][o]
    if (k == 0) {
        float bb = 0.f;
        for (int j = 0; j < CDIM; j++) {
            int idx = (n * j) & (CDIM - 1);
            bb += CT[idx] * amp_b[j] - ST[idx] * phase_b[j];
        }
        g_bias[n] = bb * sc;
    }
}

// ---------------------------------------------------------------------------
// Main GEMM: Out[b,o,p] = relu( sum_c W[o,c] * X[b,c,p] + bias[o] )
// Packed f32x2 FFMA: accumulators hold (o, o+1) pairs; X staged duplicated
// in smem (each value (x,x)) in a bank-conflict-free padded layout:
// dup row = 16 chunks, each 16 data floats + 4 pad floats (stride 20).
// Chunk tc read base = tc*20 mod 32 -> all-distinct banks per 8-lane phase.
// ---------------------------------------------------------------------------
#define FMA2(d, a, b) asm volatile("fma.rn.f32x2 %0, %1, %2, %0;" : "+l"(d) : "l"(a), "l"(b))

__global__ __launch_bounds__(256, 2)
void gemm_kernel(const float* __restrict__ X, float* __restrict__ Out) {
    extern __shared__ float sm[];
    float* Ws = sm;                    // [128][128] : Wt[c][o]
    float* Xd = sm + CDIM*CDIM;        // [KC][XROW] duplicated, padded x

    int tid = threadIdx.x;
    int b   = blockIdx.y;
    int p0  = blockIdx.x * PT;
    const float* Xb = X   + ((size_t)b * CDIM) * HW + p0;
    float*       Ob = Out + ((size_t)b * CDIM) * HW + p0;

    // load full Wt into smem (served from L2 across blocks)
    {
        const float4* src = (const float4*)g_Wt;
        float4*       dst = (float4*)Ws;
        #pragma unroll
        for (int i = 0; i < 16; i++) dst[tid + i*256] = src[tid + i*256];
    }

    ull acc[4][8];
    #pragma unroll
    for (int i = 0; i < 4; i++)
        #pragma unroll
        for (int j = 0; j < 8; j++) acc[i][j] = 0ull;   // (0.f, 0.f)

    int tr = tid >> 4;   // 0..15 : o block = tr*8
    int tc = tid & 15;   // 0..15 : p block = tc*8

    for (int c0 = 0; c0 < CDIM; c0 += KC) {
        __syncthreads();   // Ws ready (first iter) / Xd consumers done (later)
        // stage X chunk; duplicate each value into an adjacent (x,x) pair,
        // writing into the padded chunk layout
        #pragma unroll
        for (int t = 0; t < 4; t++) {
            int i   = tid + t*256;         // 0..1023
            int row = i >> 5;              // 0..31 (k within chunk)
            int c4  = i & 31;              // float4 index within 128-wide p row
            float4 v = *(const float4*)(Xb + (size_t)(c0 + row) * HW + c4*4);
            // dup logical base = c4*8 -> chunk c4>>1, offset (c4&1)*8
            int phys = (c4 >> 1)*20 + (c4 & 1)*8;
            float2* d = (float2*)(Xd + row*XROW + phys);
            d[0] = make_float2(v.x, v.x);
            d[1] = make_float2(v.y, v.y);
            d[2] = make_float2(v.z, v.z);
            d[3] = make_float2(v.w, v.w);
        }
        __syncthreads();

        #pragma unroll
        for (int k = 0; k < KC; k++) {
            const ulonglong2* wp = (const ulonglong2*)(Ws + (c0 + k)*CDIM + tr*8);
            const ulonglong2* xp = (const ulonglong2*)(Xd + k*XROW + tc*20);
            ulonglong2 wa = wp[0], wb = wp[1];          // w pairs (o,o+1)
            ulonglong2 xa = xp[0], xb = xp[1], xc = xp[2], xd = xp[3];
            ull w0 = wa.x, w1 = wa.y, w2 = wb.x, w3 = wb.y;
            ull x0 = xa.x, x1 = xa.y, x2 = xb.x, x3 = xb.y;
            ull x4 = xc.x, x5 = xc.y, x6 = xd.x, x7 = xd.y;

            FMA2(acc[0][0], w0, x0); FMA2(acc[0][1], w0, x1);
            FMA2(acc[0][2], w0, x2); FMA2(acc[0][3], w0, x3);
            FMA2(acc[0][4], w0, x4); FMA2(acc[0][5], w0, x5);
            FMA2(acc[0][6], w0, x6); FMA2(acc[0][7], w0, x7);

            FMA2(acc[1][0], w1, x0); FMA2(acc[1][1], w1, x1);
            FMA2(acc[1][2], w1, x2); FMA2(acc[1][3], w1, x3);
            FMA2(acc[1][4], w1, x4); FMA2(acc[1][5], w1, x5);
            FMA2(acc[1][6], w1, x6); FMA2(acc[1][7], w1, x7);

            FMA2(acc[2][0], w2, x0); FMA2(acc[2][1], w2, x1);
            FMA2(acc[2][2], w2, x2); FMA2(acc[2][3], w2, x3);
            FMA2(acc[2][4], w2, x4); FMA2(acc[2][5], w2, x5);
            FMA2(acc[2][6], w2, x6); FMA2(acc[2][7], w2, x7);

            FMA2(acc[3][0], w3, x0); FMA2(acc[3][1], w3, x1);
            FMA2(acc[3][2], w3, x2); FMA2(acc[3][3], w3, x3);
            FMA2(acc[3][4], w3, x4); FMA2(acc[3][5], w3, x5);
            FMA2(acc[3][6], w3, x6); FMA2(acc[3][7], w3, x7);
        }
    }

    // epilogue: + bias, relu, store
    #pragma unroll
    for (int i = 0; i < 4; i++) {
        int o0 = tr*8 + 2*i;
        float b0 = g_bias[o0];
        float b1 = g_bias[o0 + 1];
        float r0[8], r1[8];
        #pragma unroll
        for (int j = 0; j < 8; j++) {
            ull v = acc[i][j];
            float lo = __uint_as_float((unsigned)(v & 0xffffffffull));
            float hi = __uint_as_float((unsigned)(v >> 32));
            r0[j] = fmaxf(lo + b0, 0.f);
            r1[j] = fmaxf(hi + b1, 0.f);
        }
        float* po0 = Ob + (size_t)o0 * HW + tc*8;
        float* po1 = po0 + HW;
        ((float4*)po0)[0] = make_float4(r0[0], r0[1], r0[2], r0[3]);
        ((float4*)po0)[1] = make_float4(r0[4], r0[5], r0[6], r0[7]);
        ((float4*)po1)[0] = make_float4(r1[0], r1[1], r1[2], r1[3]);
        ((float4*)po1)[1] = make_float4(r1[4], r1[5], r1[6], r1[7]);
    }
}

// ---------------------------------------------------------------------------
// Launch: inputs per metadata order:
//   0: x (4*128*256*256 f32)  1: freq_mask (128)  2: amp_w (128x128)
//   3: amp_b (128)            4: phase_w (128x128) 5: phase_b (128)
// ---------------------------------------------------------------------------
extern "C" void kernel_launch(void* const* d_in, const int* in_sizes, int n_in,
                              void* d_out, int out_size) {
    const float* x       = (const float*)d_in[0];
    const float* mask    = (const float*)d_in[1];
    const float* amp_w   = (const float*)d_in[2];
    const float* amp_b   = (const float*)d_in[3];
    const float* phase_w = (const float*)d_in[4];
    const float* phase_b = (const float*)d_in[5];
    float* out = (float*)d_out;

    setup1_kernel<<<CDIM, CDIM>>>(amp_w, phase_w, mask);
    setup2_kernel<<<CDIM, CDIM>>>(amp_b, phase_b);

    cudaFuncSetAttribute(gemm_kernel,
                         cudaFuncAttributeMaxDynamicSharedMemorySize, SMEM_BYTES);
    dim3 grid(HW / PT, 4);
    gemm_kernel<<<grid, 256, SMEM_BYTES>>>(x, out);
}

// round 6
// speedup vs baseline: 1.2060x; 1.2060x over previous
#include <cuda_runtime.h>
#include <cuda_bf16.h>
#include <mma.h>
#include <cstdint>

using namespace nvcuda;

#define CDIM 128
#define HW   65536
#define NP   128                 // pixels per tile
#define NT   (4 * (HW / NP))     // 2048 tiles
#define GRID 148
#define LDW  136                 // padded bf16 row stride (mult of 8)

__device__ float          g_bias[CDIM];
__device__ unsigned short g_Whi[CDIM*CDIM];   // bf16 bits, [o][c]
__device__ unsigned short g_Wlo[CDIM*CDIM];
__device__ float g_T1[CDIM*CDIM];
__device__ float g_T2[CDIM*CDIM];

// ---------------------------------------------------------------------------
// Setup 1: T1 = amp_w @ G_re, T2 = phase_w @ G_im (algebra verified in R2)
// ---------------------------------------------------------------------------
__global__ void setup1_kernel(const float* __restrict__ amp_w,
                              const float* __restrict__ phase_w,
                              const float* __restrict__ freq_mask) {
    int o = blockIdx.x, k = threadIdx.x;
    __shared__ float AM[CDIM], PM[CDIM], CT[CDIM], ST[CDIM];
    float m = freq_mask[k];
    AM[k] = amp_w[o*CDIM + k] * m;
    PM[k] = phase_w[o*CDIM + k] * m;
    float s, c;
    sincospif(2.0f * (float)k / (float)CDIM, &s, &c);
    CT[k] = c; ST[k] = s;
    __syncthreads();
    float t1 = 0.f, t2 = 0.f;
    #pragma unroll 8
    for (int cc = 0; cc < CDIM; cc++) {
        int idx = (cc * k) & (CDIM - 1);
        t1 += AM[cc] * CT[idx];
        t2 -= PM[cc] * ST[idx];
    }
    float sgnk = (k & 1) ? -1.f : 1.f;
    g_T1[o*CDIM + k] = t1 * sgnk;
    g_T2[o*CDIM + k] = t2 * sgnk;
}

// ---------------------------------------------------------------------------
// Setup 2: W[n][k] = ((-1)^n/128) * sum_j [cos*T1 - sin*T2]; bf16 hi/lo split.
// ---------------------------------------------------------------------------
__global__ void setup2_kernel(const float* __restrict__ amp_b,
                              const float* __restrict__ phase_b) {
    int n = blockIdx.x, k = threadIdx.x;
    __shared__ float CT[CDIM], ST[CDIM];
    float s, c;
    sincospif(2.0f * (float)k / (float)CDIM, &s, &c);
    CT[k] = c; ST[k] = s;
    __syncthreads();
    float acc = 0.f;
    #pragma unroll 8
    for (int j = 0; j < CDIM; j++) {
        int idx = (n * j) & (CDIM - 1);
        acc += CT[idx] * g_T1[j*CDIM + k] - ST[idx] * g_T2[j*CDIM + k];
    }
    float sc = ((n & 1) ? -1.f : 1.f) / (float)CDIM;
    float w = acc * sc;                               // W[n][k]
    __nv_bfloat16 hi = __float2bfloat16(w);
    __nv_bfloat16 lo = __float2bfloat16(w - __bfloat162float(hi));
    g_Whi[n*CDIM + k] = __bfloat16_as_ushort(hi);
    g_Wlo[n*CDIM + k] = __bfloat16_as_ushort(lo);
    if (k == 0) {
        float bb = 0.f;
        for (int j = 0; j < CDIM; j++) {
            int idx = (n * j) & (CDIM - 1);
            bb += CT[idx] * amp_b[j] - ST[idx] * phase_b[j];
        }
        g_bias[n] = bb * sc;
    }
}

// ---------------------------------------------------------------------------
// Main GEMM via wmma (HMMA, base sm_100 ISA — tcgen05 not available in this
// toolchain's compute_100 target, per R4 ptxas log).
// Out[b,o,p] = relu( sum_c W[o,c]*X[b,c,p] + bias[o] )
// A = W (row-major [o][c]), B = X (row-major [c][p]), 3-product bf16 split:
// Wh*Xh + Wh*Xl + Wl*Xh (lo*lo dropped, ~1e-5 rel).
// Persistent CTAs; W resident in smem for the whole kernel.
// ---------------------------------------------------------------------------
// smem: Wh, Wl, Xh, Xl: 128*LDW bf16 each; biasM: 128*16 f32
#define SM_BIASM (4 * CDIM * LDW * 2)
#define SM_TOTAL (SM_BIASM + CDIM * 16 * 4)

__global__ __launch_bounds__(256, 1)
void gemm_wmma_kernel(const float* __restrict__ X, float* __restrict__ Out) {
    extern __shared__ char smraw[];
    __nv_bfloat16* Wh = (__nv_bfloat16*)smraw;
    __nv_bfloat16* Wl = Wh + CDIM*LDW;
    __nv_bfloat16* Xh = Wl + CDIM*LDW;
    __nv_bfloat16* Xl = Xh + CDIM*LDW;
    float* biasM = (float*)(smraw + SM_BIASM);   // [128][16], all cols = bias[o]

    int tid = threadIdx.x;
    int wid = tid >> 5;
    int wm = (wid & 3) * 32;    // o base of warp
    int wn = (wid >> 2) * 64;   // p base of warp

    // one-time: W hi/lo + bias matrix into smem
    for (int i = tid; i < CDIM*CDIM; i += 256) {
        int o = i >> 7, c = i & 127;
        Wh[o*LDW + c] = __ushort_as_bfloat16(g_Whi[i]);
        Wl[o*LDW + c] = __ushort_as_bfloat16(g_Wlo[i]);
    }
    for (int i = tid; i < CDIM*16; i += 256)
        biasM[i] = g_bias[i >> 4];

    for (int t = blockIdx.x; t < NT; t += GRID) {
        int b = t >> 9, p0 = (t & 511) * NP;
        const float* Xb = X + ((size_t)b * CDIM) * HW + p0;

        __syncthreads();   // W ready (first iter) / Xh,Xl readers done (later)
        // stage X tile: f32 -> bf16 hi/lo
        for (int i = tid; i < CDIM * (NP/4); i += 256) {
            int row = i >> 5, c4 = i & 31;
            float4 v = *(const float4*)(Xb + (size_t)row * HW + c4*4);
            __nv_bfloat16 h0 = __float2bfloat16(v.x);
            __nv_bfloat16 h1 = __float2bfloat16(v.y);
            __nv_bfloat16 h2 = __float2bfloat16(v.z);
            __nv_bfloat16 h3 = __float2bfloat16(v.w);
            __nv_bfloat16 l0 = __float2bfloat16(v.x - __bfloat162float(h0));
            __nv_bfloat16 l1 = __float2bfloat16(v.y - __bfloat162float(h1));
            __nv_bfloat16 l2 = __float2bfloat16(v.z - __bfloat162float(h2));
            __nv_bfloat16 l3 = __float2bfloat16(v.w - __bfloat162float(h3));
            uint2 hp, lp;
            hp.x = (uint32_t)__bfloat16_as_ushort(h0) | ((uint32_t)__bfloat16_as_ushort(h1) << 16);
            hp.y = (uint32_t)__bfloat16_as_ushort(h2) | ((uint32_t)__bfloat16_as_ushort(h3) << 16);
            lp.x = (uint32_t)__bfloat16_as_ushort(l0) | ((uint32_t)__bfloat16_as_ushort(l1) << 16);
            lp.y = (uint32_t)__bfloat16_as_ushort(l2) | ((uint32_t)__bfloat16_as_ushort(l3) << 16);
            *(uint2*)(Xh + row*LDW + c4*4) = hp;
            *(uint2*)(Xl + row*LDW + c4*4) = lp;
        }
        __syncthreads();

        // accumulators, initialized to bias (broadcast over p)
        wmma::fragment<wmma::accumulator, 16, 16, 16, float> acc[2][4];
        #pragma unroll
        for (int mi = 0; mi < 2; mi++) {
            wmma::fragment<wmma::accumulator, 16, 16, 16, float> binit;
            wmma::load_matrix_sync(binit, biasM + (wm + mi*16)*16, 16, wmma::mem_row_major);
            #pragma unroll
            for (int ni = 0; ni < 4; ni++) acc[mi][ni] = binit;
        }

        // 3 product passes: Wh*Xh, Wh*Xl, Wl*Xh
        #pragma unroll
        for (int pp = 0; pp < 3; pp++) {
            const __nv_bfloat16* A = (pp == 2) ? Wl : Wh;
            const __nv_bfloat16* B = (pp == 1) ? Xl : Xh;
            #pragma unroll
            for (int k = 0; k < CDIM; k += 16) {
                wmma::fragment<wmma::matrix_a, 16, 16, 16, __nv_bfloat16, wmma::row_major> af[2];
                wmma::load_matrix_sync(af[0], A + (wm     )*LDW + k, LDW);
                wmma::load_matrix_sync(af[1], A + (wm + 16)*LDW + k, LDW);
                wmma::fragment<wmma::matrix_b, 16, 16, 16, __nv_bfloat16, wmma::row_major> bfr[4];
                #pragma unroll
                for (int ni = 0; ni < 4; ni++)
                    wmma::load_matrix_sync(bfr[ni], B + (size_t)k*LDW + wn + ni*16, LDW);
                #pragma unroll
                for (int mi = 0; mi < 2; mi++)
                    #pragma unroll
                    for (int ni = 0; ni < 4; ni++)
                        wmma::mma_sync(acc[mi][ni], af[mi], bfr[ni], acc[mi][ni]);
            }
        }

        // epilogue: relu (elementwise, position-independent) + store to gmem
        #pragma unroll
        for (int mi = 0; mi < 2; mi++) {
            #pragma unroll
            for (int ni = 0; ni < 4; ni++) {
                #pragma unroll
                for (int e = 0; e < acc[mi][ni].num_elements; e++)
                    acc[mi][ni].x[e] = fmaxf(acc[mi][ni].x[e], 0.f);
                float* Op = Out + ((size_t)(b*CDIM) + wm + mi*16) * HW + p0 + wn + ni*16;
                wmma::store_matrix_sync(Op, acc[mi][ni], HW, wmma::mem_row_major);
            }
        }
    }
}

// ---------------------------------------------------------------------------
extern "C" void kernel_launch(void* const* d_in, const int* in_sizes, int n_in,
                              void* d_out, int out_size) {
    const float* x       = (const float*)d_in[0];
    const float* mask    = (const float*)d_in[1];
    const float* amp_w   = (const float*)d_in[2];
    const float* amp_b   = (const float*)d_in[3];
    const float* phase_w = (const float*)d_in[4];
    const float* phase_b = (const float*)d_in[5];
    float* out = (float*)d_out;

    setup1_kernel<<<CDIM, CDIM>>>(amp_w, phase_w, mask);
    setup2_kernel<<<CDIM, CDIM>>>(amp_b, phase_b);

    cudaFuncSetAttribute(gemm_wmma_kernel,
                         cudaFuncAttributeMaxDynamicSharedMemorySize, SM_TOTAL);
    gemm_wmma_kernel<<<GRID, 256, SM_TOTAL>>>(x, out);
}

// round 9
// speedup vs baseline: 1.6778x; 1.3912x over previous
#include <cuda_runtime.h>
#include <cuda_bf16.h>
#include <mma.h>
#include <cstdint>

using namespace nvcuda;

#define CDIM 128
#define HW   65536
#define NP   128                 // pixels per tile
#define NT   (4 * (HW / NP))     // 2048 tiles
#define GRID 148
#define LDW  136                 // padded bf16 row stride (mult of 8)

__device__ float          g_bias[CDIM];
__device__ unsigned short g_Whi[CDIM*CDIM];   // bf16 bits, [o][c]
__device__ unsigned short g_Wlo[CDIM*CDIM];
__device__ float g_T1[CDIM*CDIM];
__device__ float g_T2[CDIM*CDIM];

// ---------------------------------------------------------------------------
// Setup 1: T1 = amp_w @ G_re, T2 = phase_w @ G_im (algebra verified in R2)
// ---------------------------------------------------------------------------
__global__ void setup1_kernel(const float* __restrict__ amp_w,
                              const float* __restrict__ phase_w,
                              const float* __restrict__ freq_mask) {
    int o = blockIdx.x, k = threadIdx.x;
    __shared__ float AM[CDIM], PM[CDIM], CT[CDIM], ST[CDIM];
    float m = freq_mask[k];
    AM[k] = amp_w[o*CDIM + k] * m;
    PM[k] = phase_w[o*CDIM + k] * m;
    float s, c;
    sincospif(2.0f * (float)k / (float)CDIM, &s, &c);
    CT[k] = c; ST[k] = s;
    __syncthreads();
    float t1 = 0.f, t2 = 0.f;
    #pragma unroll 8
    for (int cc = 0; cc < CDIM; cc++) {
        int idx = (cc * k) & (CDIM - 1);
        t1 += AM[cc] * CT[idx];
        t2 -= PM[cc] * ST[idx];
    }
    float sgnk = (k & 1) ? -1.f : 1.f;
    g_T1[o*CDIM + k] = t1 * sgnk;
    g_T2[o*CDIM + k] = t2 * sgnk;
}

// ---------------------------------------------------------------------------
// Setup 2: W[n][k] = ((-1)^n/128) * sum_j [cos*T1 - sin*T2]; bf16 hi/lo split.
// ---------------------------------------------------------------------------
__global__ void setup2_kernel(const float* __restrict__ amp_b,
                              const float* __restrict__ phase_b) {
    int n = blockIdx.x, k = threadIdx.x;
    __shared__ float CT[CDIM], ST[CDIM];
    float s, c;
    sincospif(2.0f * (float)k / (float)CDIM, &s, &c);
    CT[k] = c; ST[k] = s;
    __syncthreads();
    float acc = 0.f;
    #pragma unroll 8
    for (int j = 0; j < CDIM; j++) {
        int idx = (n * j) & (CDIM - 1);
        acc += CT[idx] * g_T1[j*CDIM + k] - ST[idx] * g_T2[j*CDIM + k];
    }
    float sc = ((n & 1) ? -1.f : 1.f) / (float)CDIM;
    float w = acc * sc;                               // W[n][k]
    __nv_bfloat16 hi = __float2bfloat16(w);
    __nv_bfloat16 lo = __float2bfloat16(w - __bfloat162float(hi));
    g_Whi[n*CDIM + k] = __bfloat16_as_ushort(hi);
    g_Wlo[n*CDIM + k] = __bfloat16_as_ushort(lo);
    if (k == 0) {
        float bb = 0.f;
        for (int j = 0; j < CDIM; j++) {
            int idx = (n * j) & (CDIM - 1);
            bb += CT[idx] * amp_b[j] - ST[idx] * phase_b[j];
        }
        g_bias[n] = bb * sc;
    }
}

// ---------------------------------------------------------------------------
// Packed helpers
// ---------------------------------------------------------------------------
__device__ __forceinline__ uint32_t cvt_bf16x2(float hi, float lo) {
    uint32_t r;
    asm("cvt.rn.bf16x2.f32 %0, %1, %2;" : "=r"(r) : "f"(hi), "f"(lo));
    return r;
}
__device__ __forceinline__ void cp_async16(uint32_t saddr, const void* g) {
    asm volatile("cp.async.cg.shared.global [%0], [%1], 16;" :: "r"(saddr), "l"(g));
}
__device__ __forceinline__ uint32_t smem_u32(const void* p) {
    uint32_t a;
    asm("{ .reg .u64 t; cvta.to.shared.u64 t, %1; cvt.u32.u64 %0, t; }" : "=r"(a) : "l"(p));
    return a;
}

// smem layout (bytes)
#define OFF_WH   0
#define OFF_WL   34816
#define OFF_XH   69632
#define OFF_XL   104448
#define OFF_RAW  139264                 // 128 rows x 128 f32 (512B rows)
#define OFF_BIAS 204800
#define SM_TOTAL 212992

// ---------------------------------------------------------------------------
// Main GEMM via wmma (HMMA; tcgen05 unavailable on this toolchain's
// compute_100 target). Out[b,o,p] = relu( sum_c W[o,c]*X[b,c,p] + bias[o] )
// 3-product bf16 split: Wh*Xh + Wl*Xh + Wh*Xl. Persistent CTAs; W in smem.
// cp.async double-buffers X (raw f32 staging buffer) to hide DRAM latency.
// ---------------------------------------------------------------------------
__global__ __launch_bounds__(256, 1)
void gemm_wmma_kernel(const float* __restrict__ X, float* __restrict__ Out) {
    extern __shared__ char smraw[];
    __nv_bfloat16* Wh = (__nv_bfloat16*)(smraw + OFF_WH);
    __nv_bfloat16* Wl = (__nv_bfloat16*)(smraw + OFF_WL);
    __nv_bfloat16* Xh = (__nv_bfloat16*)(smraw + OFF_XH);
    __nv_bfloat16* Xl = (__nv_bfloat16*)(smraw + OFF_XL);
    float*         Rw = (float*)(smraw + OFF_RAW);
    float*      biasM = (float*)(smraw + OFF_BIAS);   // [128][16]

    int tid = threadIdx.x;
    int wid = tid >> 5;
    int wm = (wid & 3) * 32;    // o base of warp
    int wn = (wid >> 2) * 64;   // p base of warp
    uint32_t raw_s = smem_u32(Rw);

    // one-time: W hi/lo + bias matrix into smem
    for (int i = tid; i < CDIM*CDIM; i += 256) {
        int o = i >> 7, c = i & 127;
        Wh[o*LDW + c] = __ushort_as_bfloat16(g_Whi[i]);
        Wl[o*LDW + c] = __ushort_as_bfloat16(g_Wlo[i]);
    }
    for (int i = tid; i < CDIM*16; i += 256)
        biasM[i] = g_bias[i >> 4];

    // ---- prologue: cp.async tile0 -> raw, convert to bf16 ----
    int t = blockIdx.x;
    {
        int b = t >> 9, p0 = (t & 511) * NP;
        const float* Xb = X + ((size_t)b * CDIM) * HW + p0;
        #pragma unroll
        for (int it = 0; it < 16; it++) {
            int i = tid + it*256, row = i >> 5, c4 = i & 31;
            cp_async16(raw_s + row*512 + c4*16, Xb + (size_t)row * HW + c4*4);
        }
        asm volatile("cp.async.commit_group;" ::: "memory");
        asm volatile("cp.async.wait_group 0;" ::: "memory");
    }
    __syncthreads();
    // convert raw -> Xh/Xl
    #pragma unroll
    for (int it = 0; it < 16; it++) {
        int i = tid + it*256, row = i >> 5, c4 = i & 31;
        float4 v = *(const float4*)(Rw + row*128 + c4*4);
        uint32_t h0 = cvt_bf16x2(v.y, v.x);
        uint32_t h1 = cvt_bf16x2(v.w, v.z);
        float f0 = __uint_as_float(h0 << 16);
        float f1 = __uint_as_float(h0 & 0xffff0000u);
        float f2 = __uint_as_float(h1 << 16);
        float f3 = __uint_as_float(h1 & 0xffff0000u);
        uint32_t l0 = cvt_bf16x2(v.y - f1, v.x - f0);
        uint32_t l1 = cvt_bf16x2(v.w - f3, v.z - f2);
        *(uint2*)(Xh + row*LDW + c4*4) = make_uint2(h0, h1);
        *(uint2*)(Xl + row*LDW + c4*4) = make_uint2(l0, l1);
    }
    __syncthreads();

    for (; t < NT; t += GRID) {
        int b = t >> 9, p0 = (t & 511) * NP;
        int tn = t + GRID;

        // ---- 1. prefetch next tile into raw buffer (overlaps MMA) ----
        if (tn < NT) {
            int bn = tn >> 9, pn = (tn & 511) * NP;
            const float* Xb = X + ((size_t)bn * CDIM) * HW + pn;
            #pragma unroll
            for (int it = 0; it < 16; it++) {
                int i = tid + it*256, row = i >> 5, c4 = i & 31;
                cp_async16(raw_s + row*512 + c4*16, Xb + (size_t)row * HW + c4*4);
            }
        }
        asm volatile("cp.async.commit_group;" ::: "memory");

        // ---- 2. MMA: 3-product fused k-loop ----
        wmma::fragment<wmma::accumulator, 16, 16, 16, float> acc[2][4];
        #pragma unroll
        for (int mi = 0; mi < 2; mi++) {
            wmma::fragment<wmma::accumulator, 16, 16, 16, float> binit;
            wmma::load_matrix_sync(binit, biasM + (wm + mi*16)*16, 16, wmma::mem_row_major);
            #pragma unroll
            for (int ni = 0; ni < 4; ni++) acc[mi][ni] = binit;
        }
        #pragma unroll
        for (int k = 0; k < CDIM; k += 16) {
            wmma::fragment<wmma::matrix_a, 16, 16, 16, __nv_bfloat16, wmma::row_major> ah[2], al[2];
            wmma::load_matrix_sync(ah[0], Wh + (wm     )*LDW + k, LDW);
            wmma::load_matrix_sync(ah[1], Wh + (wm + 16)*LDW + k, LDW);
            wmma::load_matrix_sync(al[0], Wl + (wm     )*LDW + k, LDW);
            wmma::load_matrix_sync(al[1], Wl + (wm + 16)*LDW + k, LDW);
            {
                wmma::fragment<wmma::matrix_b, 16, 16, 16, __nv_bfloat16, wmma::row_major> bh[4];
                #pragma unroll
                for (int ni = 0; ni < 4; ni++)
                    wmma::load_matrix_sync(bh[ni], Xh + (size_t)k*LDW + wn + ni*16, LDW);
                #pragma unroll
                for (int mi = 0; mi < 2; mi++)
                    #pragma unroll
                    for (int ni = 0; ni < 4; ni++) {
                        wmma::mma_sync(acc[mi][ni], ah[mi], bh[ni], acc[mi][ni]);
                        wmma::mma_sync(acc[mi][ni], al[mi], bh[ni], acc[mi][ni]);
                    }
            }
            {
                wmma::fragment<wmma::matrix_b, 16, 16, 16, __nv_bfloat16, wmma::row_major> bl[4];
                #pragma unroll
                for (int ni = 0; ni < 4; ni++)
                    wmma::load_matrix_sync(bl[ni], Xl + (size_t)k*LDW + wn + ni*16, LDW);
                #pragma unroll
                for (int mi = 0; mi < 2; mi++)
                    #pragma unroll
                    for (int ni = 0; ni < 4; ni++)
                        wmma::mma_sync(acc[mi][ni], ah[mi], bl[ni], acc[mi][ni]);
            }
        }

        // ---- 3. epilogue: relu + store ----
        #pragma unroll
        for (int mi = 0; mi < 2; mi++) {
            #pragma unroll
            for (int ni = 0; ni < 4; ni++) {
                #pragma unroll
                for (int e = 0; e < acc[mi][ni].num_elements; e++)
                    acc[mi][ni].x[e] = fmaxf(acc[mi][ni].x[e], 0.f);
                float* Op = Out + ((size_t)(b*CDIM) + wm + mi*16) * HW + p0 + wn + ni*16;
                wmma::store_matrix_sync(Op, acc[mi][ni], HW, wmma::mem_row_major);
            }
        }

        // ---- 4. land prefetch, convert raw -> Xh/Xl for next tile ----
        asm volatile("cp.async.wait_group 0;" ::: "memory");
        __syncthreads();            // MMA reads of Xh/Xl done; raw landed
        if (tn < NT) {
            #pragma unroll
            for (int it = 0; it < 16; it++) {
                int i = tid + it*256, row = i >> 5, c4 = i & 31;
                float4 v = *(const float4*)(Rw + row*128 + c4*4);
                uint32_t h0 = cvt_bf16x2(v.y, v.x);
                uint32_t h1 = cvt_bf16x2(v.w, v.z);
                float f0 = __uint_as_float(h0 << 16);
                float f1 = __uint_as_float(h0 & 0xffff0000u);
                float f2 = __uint_as_float(h1 << 16);
                float f3 = __uint_as_float(h1 & 0xffff0000u);
                uint32_t l0 = cvt_bf16x2(v.y - f1, v.x - f0);
                uint32_t l1 = cvt_bf16x2(v.w - f3, v.z - f2);
                *(uint2*)(Xh + row*LDW + c4*4) = make_uint2(h0, h1);
                *(uint2*)(Xl + row*LDW + c4*4) = make_uint2(l0, l1);
            }
        }
        __syncthreads();            // converted tile visible to all warps
    }
}

// ---------------------------------------------------------------------------
extern "C" void kernel_launch(void* const* d_in, const int* in_sizes, int n_in,
                              void* d_out, int out_size) {
    const float* x       = (const float*)d_in[0];
    const float* mask    = (const float*)d_in[1];
    const float* amp_w   = (const float*)d_in[2];
    const float* amp_b   = (const float*)d_in[3];
    const float* phase_w = (const float*)d_in[4];
    const float* phase_b = (const float*)d_in[5];
    float* out = (float*)d_out;

    setup1_kernel<<<CDIM, CDIM>>>(amp_w, phase_w, mask);
    setup2_kernel<<<CDIM, CDIM>>>(amp_b, phase_b);

    cudaFuncSetAttribute(gemm_wmma_kernel,
                         cudaFuncAttributeMaxDynamicSharedMemorySize, SM_TOTAL);
    gemm_wmma_kernel<<<GRID, 256, SM_TOTAL>>>(x, out);
}